// round 9
// baseline (speedup 1.0000x reference)
#include <cuda_runtime.h>

// SyntheticTripletLoss closed form: per valid row only
//   pp=<p,p>, tt=<t,t>, pt=<p,t>
//   sim_pn = (pp - pt^2) / max(sqrt(pp - 2pt^2 + pt^2*tt), EPS)
//   loss   = max(MARGIN + sim_pn - pt, 0); mean over valid rows.
//
// R9: perfect load balance. Warps are assigned ONLY to valid rows (prefix-sum
// over lengths + binary search), so every resident warp streams a full 4KB.
// Invalid tail blocks exit immediately and recycle their CTA slots. Tests the
// "wasted warp slots / wave imbalance" hypothesis for the 2.5 TB/s wall.

#define MARGIN 0.5f
#define EPS_N 1e-12f

static constexpr int B = 32;
static constexpr int T = 512;
static constexpr int D = 512;
static constexpr int WARPS_PER_BLOCK = 8;
static constexpr int THREADS = WARPS_PER_BLOCK * 32;    // 256
static constexpr int ROWS = B * T;                      // 16384
static constexpr int NBLOCKS = ROWS / WARPS_PER_BLOCK;  // 2048 (worst case)

__device__ float g_partials[NBLOCKS];
__device__ unsigned int g_ticket;   // zero-init; last block resets each run

__global__ __launch_bounds__(THREADS)
void triplet_balanced_kernel(const float* __restrict__ preds,
                             const float* __restrict__ targets,
                             const int* __restrict__ lengths,
                             float* __restrict__ out) {
    __shared__ int   s_pre[B + 1];            // exclusive prefix of lengths
    __shared__ float s_warp[WARPS_PER_BLOCK];
    __shared__ bool  s_is_last;

    const int warp = threadIdx.x >> 5;
    const int lane = threadIdx.x & 31;

    // Warp 0: inclusive shuffle-scan of lengths[0..31] -> prefix in smem.
    if (warp == 0) {
        int v = __ldg(&lengths[lane]);
        int s = v;
        #pragma unroll
        for (int off = 1; off < 32; off <<= 1) {
            int n = __shfl_up_sync(0xffffffffu, s, off);
            if (lane >= off) s += n;
        }
        s_pre[lane + 1] = s;          // inclusive -> pre[i+1]
        if (lane == 0) s_pre[0] = 0;
    }
    __syncthreads();

    const int total = s_pre[B];       // number of valid rows
    const int vid   = blockIdx.x * WARPS_PER_BLOCK + warp;

    float loss = 0.0f;

    if (vid < total) {
        // binary search: largest b with s_pre[b] <= vid
        int lo = 0, hi = B;           // invariant: s_pre[lo] <= vid < s_pre[hi]
        #pragma unroll
        for (int i = 0; i < 5; i++) { // log2(32)
            int mid = (lo + hi) >> 1;
            if (s_pre[mid] <= vid) lo = mid; else hi = mid;
        }
        const int b   = lo;
        const int t   = vid - s_pre[b];
        const int row = b * T + t;

        const float4* __restrict__ p4 =
            reinterpret_cast<const float4*>(preds + (size_t)row * D);
        const float4* __restrict__ t4 =
            reinterpret_cast<const float4*>(targets + (size_t)row * D);

        float4 a0 = __ldg(p4 + lane);
        float4 a1 = __ldg(p4 + lane + 32);
        float4 a2 = __ldg(p4 + lane + 64);
        float4 a3 = __ldg(p4 + lane + 96);
        float4 c0 = __ldg(t4 + lane);
        float4 c1 = __ldg(t4 + lane + 32);
        float4 c2 = __ldg(t4 + lane + 64);
        float4 c3 = __ldg(t4 + lane + 96);

        float pp = 0.f, tt = 0.f, pt = 0.f;
        #define ACC(a, c)                                                        \
            pp = fmaf(a.x, a.x, fmaf(a.y, a.y, fmaf(a.z, a.z, fmaf(a.w, a.w, pp)))); \
            tt = fmaf(c.x, c.x, fmaf(c.y, c.y, fmaf(c.z, c.z, fmaf(c.w, c.w, tt)))); \
            pt = fmaf(a.x, c.x, fmaf(a.y, c.y, fmaf(a.z, c.z, fmaf(a.w, c.w, pt))));
        ACC(a0, c0) ACC(a1, c1) ACC(a2, c2) ACC(a3, c3)
        #undef ACC

        #pragma unroll
        for (int off = 16; off; off >>= 1) {
            pp += __shfl_xor_sync(0xffffffffu, pp, off);
            tt += __shfl_xor_sync(0xffffffffu, tt, off);
            pt += __shfl_xor_sync(0xffffffffu, pt, off);
        }

        float pt2  = pt * pt;
        float n2   = fmaxf(pp - 2.0f * pt2 + pt2 * tt, 0.0f);
        float norm = fmaxf(sqrtf(n2), EPS_N);
        loss = fmaxf(MARGIN + (pp - pt2) / norm - pt, 0.0f);
    }

    // ---- block partial (fixed slot: deterministic) + acq_rel ticket ----
    if (lane == 0) s_warp[warp] = loss;
    __syncthreads();

    if (threadIdx.x == 0) {
        float sum = 0.f;
        #pragma unroll
        for (int i = 0; i < WARPS_PER_BLOCK; i++) sum += s_warp[i];
        g_partials[blockIdx.x] = sum;
        unsigned int old;
        asm volatile("atom.acq_rel.gpu.global.add.u32 %0, [%1], 1;"
                     : "=r"(old) : "l"(&g_ticket) : "memory");
        s_is_last = (old == (unsigned int)(NBLOCKS - 1));
    }
    __syncthreads();
    if (!s_is_last) return;

    // ---- last block: reduce 2048 partials (L2-resident), fixed order ----
    __shared__ float s_red[THREADS];
    float sum = 0.f;
    #pragma unroll
    for (int k = 0; k < NBLOCKS / THREADS; k++)
        sum += __ldcg(&g_partials[threadIdx.x + k * THREADS]);
    s_red[threadIdx.x] = sum;
    __syncthreads();
    #pragma unroll
    for (int off = THREADS / 2; off; off >>= 1) {
        if (threadIdx.x < off) s_red[threadIdx.x] += s_red[threadIdx.x + off];
        __syncthreads();
    }
    if (threadIdx.x == 0) {
        out[0] = s_red[0] / (float)total;
        g_ticket = 0;   // reset for next graph replay
    }
}

extern "C" void kernel_launch(void* const* d_in, const int* in_sizes, int n_in,
                              void* d_out, int out_size) {
    const float* preds   = (const float*)d_in[0];
    const float* targets = (const float*)d_in[1];
    const int*   lengths = (const int*)d_in[2];
    float* out = (float*)d_out;

    triplet_balanced_kernel<<<NBLOCKS, THREADS>>>(preds, targets, lengths, out);
}